// round 4
// baseline (speedup 1.0000x reference)
#include <cuda_runtime.h>
#include <math.h>

#define BN    8
#define SSUP  25
#define TTGT  75
#define CCLS  5
#define NIMG  800     // 200 support + 600 target
#define NSUP  200
#define DFEAT 2304
#define EPSN  1e-8f

// Scratch (no allocations allowed -> device globals, referenced directly in device code)
__device__ float g_a1[NIMG * 64 * 42 * 42];   // ~361 MB
__device__ float g_a2[NIMG * 64 * 21 * 21];   // ~90 MB
__device__ float g_a3[NIMG * 64 * 11 * 11];   // ~25 MB
__device__ float g_emb[NIMG * DFEAT];         // ~7.4 MB
__device__ float g_protos[BN * CCLS * DFEAT];
__device__ float g_pnorm[BN * CCLS];

// Direct conv, stride 2, 3x3, SAME padding (pad_lo = PAD per layer).
// One block = one (image, group of 8 output channels). Weights for the group
// (8*CIN*9 floats) are staged in shared memory; input read via __ldg (L1).
// Each thread computes 8 output channels x 4 consecutive output columns.
template <int CIN, int HIN, int HOUT, int PAD, int TPB>
__device__ __forceinline__ void conv_body(
    const float* __restrict__ base,    // image-local input  [CIN,HIN,HIN]
    const float* __restrict__ W,       // [64,CIN,3,3]
    const float* __restrict__ bias,    // [64]
    float* __restrict__ outp,          // image-local output [64,HOUT,HOUT]
    int cog, int task)
{
    constexpr int WT = (HOUT + 3) / 4;
    const int tid = threadIdx.x;

    __shared__ float sw[8 * CIN * 9];
    for (int i = tid; i < 8 * CIN * 9; i += TPB)
        sw[i] = __ldg(W + (size_t)cog * CIN * 9 + i);
    __syncthreads();

    if (task >= HOUT * WT) return;
    const int h  = task / WT;
    const int w0 = (task % WT) * 4;
    const int r0 = 2 * h  - PAD;
    const int c0 = 2 * w0 - PAD;

    float acc[8][4];
#pragma unroll
    for (int oc = 0; oc < 8; oc++)
#pragma unroll
        for (int p = 0; p < 4; p++) acc[oc][p] = 0.f;

    for (int cin = 0; cin < CIN; cin++) {
        const float* ip = base + (size_t)cin * HIN * HIN;
        float iv[3][9];
#pragma unroll
        for (int kh = 0; kh < 3; kh++) {
            const int r = r0 + kh;
            const bool rok = (r >= 0) && (r < HIN);
#pragma unroll
            for (int kc = 0; kc < 9; kc++) {
                const int c = c0 + kc;
                iv[kh][kc] = (rok && c >= 0 && c < HIN) ? __ldg(ip + r * HIN + c) : 0.f;
            }
        }
        const float* wrow = &sw[cin * 9];
#pragma unroll
        for (int oc = 0; oc < 8; oc++) {
            float wt[9];
#pragma unroll
            for (int k = 0; k < 9; k++) wt[k] = wrow[(size_t)oc * CIN * 9 + k];
#pragma unroll
            for (int p = 0; p < 4; p++)
#pragma unroll
                for (int kh = 0; kh < 3; kh++)
#pragma unroll
                    for (int kw = 0; kw < 3; kw++)
                        acc[oc][p] += iv[kh][2 * p + kw] * wt[kh * 3 + kw];
        }
    }

#pragma unroll
    for (int oc = 0; oc < 8; oc++) {
        const int co = cog + oc;
        const float bi = __ldg(bias + co);
#pragma unroll
        for (int p = 0; p < 4; p++) {
            const int w = w0 + p;
            if (w < HOUT)
                outp[((size_t)co * HOUT + h) * HOUT + w] = fmaxf(acc[oc][p] + bi, 0.f);
        }
    }
}

// Layer 1: inputs come from the two harness buffers (support | target).
__global__ void conv1_k(const float* __restrict__ xs, const float* __restrict__ xt,
                        const float* __restrict__ W, const float* __restrict__ b)
{
    const int n   = blockIdx.z;
    const int cog = blockIdx.y * 8;
    const int task = blockIdx.x * 128 + threadIdx.x;
    const float* base = (n < NSUP) ? xs + (size_t)n * 3 * 84 * 84
                                   : xt + (size_t)(n - NSUP) * 3 * 84 * 84;
    conv_body<3, 84, 42, 0, 128>(base, W, b, g_a1 + (size_t)n * 64 * 42 * 42, cog, task);
}

__global__ void conv2_k(const float* __restrict__ W, const float* __restrict__ b)
{
    const int n = blockIdx.y, cog = blockIdx.x * 8;
    conv_body<64, 42, 21, 0, 128>(g_a1 + (size_t)n * 64 * 42 * 42, W, b,
                                  g_a2 + (size_t)n * 64 * 21 * 21, cog, threadIdx.x);
}

__global__ void conv3_k(const float* __restrict__ W, const float* __restrict__ b)
{
    const int n = blockIdx.y, cog = blockIdx.x * 8;
    conv_body<64, 21, 11, 1, 64>(g_a2 + (size_t)n * 64 * 21 * 21, W, b,
                                 g_a3 + (size_t)n * 64 * 11 * 11, cog, threadIdx.x);
}

__global__ void conv4_k(const float* __restrict__ W, const float* __restrict__ b)
{
    const int n = blockIdx.y, cog = blockIdx.x * 8;
    conv_body<64, 11, 6, 1, 32>(g_a3 + (size_t)n * 64 * 11 * 11, W, b,
                                g_emb + (size_t)n * DFEAT, cog, threadIdx.x);
}

// Prototypes: proto[b][c][d] = sum_{s: y[b,s]%5==c} emb[b,s,d] / CAP,  CAP=5.
// Also computes ||proto|| per (b,c).  grid = 40 blocks, 256 threads.
__global__ void proto_k(const int* __restrict__ y)
{
    const int b = blockIdx.x / CCLS;
    const int c = blockIdx.x % CCLS;
    const int tid = threadIdx.x;
    __shared__ float sel[SSUP];
    if (tid < SSUP)
        sel[tid] = ((y[b * SSUP + tid] % CCLS) == c) ? 0.2f : 0.f;  // 1/CAP folded in
    __syncthreads();

    float sq = 0.f;
    for (int d = tid; d < DFEAT; d += 256) {
        float s = 0.f;
#pragma unroll 5
        for (int k = 0; k < SSUP; k++)
            s += sel[k] * g_emb[(size_t)(b * SSUP + k) * DFEAT + d];
        g_protos[(size_t)(b * CCLS + c) * DFEAT + d] = s;
        sq += s * s;
    }
    __shared__ float red[256];
    red[tid] = sq;
    __syncthreads();
    for (int off = 128; off > 0; off >>= 1) {
        if (tid < off) red[tid] += red[tid + off];
        __syncthreads();
    }
    if (tid == 0) g_pnorm[blockIdx.x] = sqrtf(red[0]);
}

// Cosine logits: out[b,t,c] = (t . p_c) / (max(|t|,eps) * max(|p_c|,eps))
// grid = 600 blocks (one per (b,t)), 128 threads.
__global__ void preds_k(float* __restrict__ out)
{
    const int bt = blockIdx.x;
    const int b  = bt / TTGT;
    const int tid = threadIdx.x;
    const float* te = g_emb + (size_t)(NSUP + bt) * DFEAT;
    const float* pr = g_protos + (size_t)b * CCLS * DFEAT;

    float dot[CCLS] = {0.f, 0.f, 0.f, 0.f, 0.f};
    float nn = 0.f;
    for (int d = tid; d < DFEAT; d += 128) {
        const float tv = te[d];
        nn += tv * tv;
#pragma unroll
        for (int c = 0; c < CCLS; c++)
            dot[c] += tv * pr[(size_t)c * DFEAT + d];
    }

    __shared__ float red[6][128];
    red[0][tid] = nn;
#pragma unroll
    for (int c = 0; c < CCLS; c++) red[c + 1][tid] = dot[c];
    __syncthreads();
    for (int off = 64; off > 0; off >>= 1) {
        if (tid < off) {
#pragma unroll
            for (int j = 0; j < 6; j++) red[j][tid] += red[j][tid + off];
        }
        __syncthreads();
    }
    if (tid < CCLS) {
        const float tn = fmaxf(sqrtf(red[0][0]), EPSN);
        const float pn = fmaxf(g_pnorm[b * CCLS + tid], EPSN);
        out[bt * CCLS + tid] = red[1 + tid][0] / (tn * pn);
    }
}

extern "C" void kernel_launch(void* const* d_in, const int* in_sizes, int n_in,
                              void* d_out, int out_size)
{
    (void)in_sizes; (void)n_in; (void)out_size;
    const float* xs = (const float*)d_in[0];   // [8,25,3,84,84]
    const float* xt = (const float*)d_in[1];   // [8,75,3,84,84]
    const int*   y  = (const int*)d_in[2];     // [8,25]
    const float* W1 = (const float*)d_in[3];
    const float* b1 = (const float*)d_in[4];
    const float* W2 = (const float*)d_in[5];
    const float* b2 = (const float*)d_in[6];
    const float* W3 = (const float*)d_in[7];
    const float* b3 = (const float*)d_in[8];
    const float* W4 = (const float*)d_in[9];
    const float* b4 = (const float*)d_in[10];
    float* out = (float*)d_out;

    // Layer 1: 3x84x84 -> 64x42x42, pad lo=0 ; tasks = 42*11 = 462
    conv1_k<<<dim3(4, 8, NIMG), 128>>>(xs, xt, W1, b1);
    // Layer 2: 64x42x42 -> 64x21x21, pad lo=0 ; tasks = 21*6 = 126
    conv2_k<<<dim3(8, NIMG), 128>>>(W2, b2);
    // Layer 3: 64x21x21 -> 64x11x11, pad lo=1 ; tasks = 11*3 = 33
    conv3_k<<<dim3(8, NIMG), 64>>>(W3, b3);
    // Layer 4: 64x11x11 -> 64x6x6,  pad lo=1 ; tasks = 6*2 = 12
    conv4_k<<<dim3(8, NIMG), 32>>>(W4, b4);

    proto_k<<<BN * CCLS, 256>>>(y);
    preds_k<<<BN * TTGT, 128>>>(out);
}

// round 6
// speedup vs baseline: 1.2931x; 1.2931x over previous
#include <cuda_runtime.h>
#include <math.h>

#define BN    8
#define SSUP  25
#define TTGT  75
#define CCLS  5
#define NIMG  800     // 200 support + 600 target
#define NSUP  200
#define DFEAT 2304
#define EPSN  1e-8f

typedef unsigned long long u64;

// Scratch (no allocations allowed -> device globals, referenced directly in device code)
__device__ float g_a1[NIMG * 64 * 42 * 42];   // ~361 MB
__device__ float g_a2[NIMG * 64 * 21 * 21];   // ~90 MB
__device__ float g_a3[NIMG * 64 * 11 * 11];   // ~25 MB
__device__ float g_emb[NIMG * DFEAT];         // ~7.4 MB
__device__ float g_protos[BN * CCLS * DFEAT];
__device__ float g_pnorm[BN * CCLS];

// ---- packed f32x2 helpers (sm_103a FFMA2 path) ----
__device__ __forceinline__ u64 dup2(float v) {
    u64 r; unsigned u = __float_as_uint(v);
    asm("mov.b64 %0, {%1, %2};" : "=l"(r) : "r"(u), "r"(u));
    return r;
}
__device__ __forceinline__ u64 fma2(u64 a, u64 b, u64 c) {
    u64 d;
    asm("fma.rn.f32x2 %0, %1, %2, %3;" : "=l"(d) : "l"(a), "l"(b), "l"(c));
    return d;
}
__device__ __forceinline__ float2 unpack2(u64 v) {
    unsigned lo, hi;
    asm("mov.b64 {%0, %1}, %2;" : "=r"(lo), "=r"(hi) : "l"(v));
    return make_float2(__uint_as_float(lo), __uint_as_float(hi));
}

// Direct conv, stride 2, 3x3, SAME padding (pad_lo = PAD per layer).
// Weights for an 8-channel cout group staged in smem as [cin][k][oc] (oc
// fastest) so an (oc,oc+1) pair is one aligned LDS.64. Math uses packed
// fma.rn.f32x2: 4 oc-pairs x 4 output pixels per thread.
template <int CIN, int HIN, int HOUT, int PAD, int TPB>
__device__ __forceinline__ void conv_body(
    const float* __restrict__ base,    // image-local input  [CIN,HIN,HIN]
    const float* __restrict__ W,       // [64,CIN,3,3]
    const float* __restrict__ bias,    // [64]
    float* __restrict__ outp,          // image-local output [64,HOUT,HOUT]
    int cog, int task)
{
    constexpr int WT = (HOUT + 3) / 4;
    constexpr int NW = 8 * CIN * 9;
    const int tid = threadIdx.x;

    __shared__ __align__(16) float sw[NW];   // [cin][k][oc]
    for (int i = tid; i < NW; i += TPB) {
        const int oc  = i & 7;
        const int k   = (i >> 3) % 9;
        const int cin = i / 72;
        sw[i] = __ldg(W + ((size_t)(cog + oc) * CIN + cin) * 9 + k);
    }
    __syncthreads();

    if (task < 0 || task >= HOUT * WT) return;
    const int h  = task / WT;
    const int w0 = (task % WT) * 4;
    const int r0 = 2 * h  - PAD;
    const int c0 = 2 * w0 - PAD;

    u64 acc[4][4];
#pragma unroll
    for (int q = 0; q < 4; q++)
#pragma unroll
        for (int p = 0; p < 4; p++) acc[q][p] = 0ull;

    for (int cin = 0; cin < CIN; cin++) {
        const float* ip = base + (size_t)cin * HIN * HIN;
#pragma unroll
        for (int kh = 0; kh < 3; kh++) {
            const int r = r0 + kh;
            const bool rok = (r >= 0) && (r < HIN);
            u64 dv[9];
#pragma unroll
            for (int kc = 0; kc < 9; kc++) {
                const int c = c0 + kc;
                const float v = (rok && c >= 0 && c < HIN) ? __ldg(ip + r * HIN + c) : 0.f;
                dv[kc] = dup2(v);
            }
#pragma unroll
            for (int kw = 0; kw < 3; kw++) {
                const u64* wrow = (const u64*)&sw[cin * 72 + (kh * 3 + kw) * 8];
#pragma unroll
                for (int q = 0; q < 4; q++) {
                    const u64 wp = wrow[q];
#pragma unroll
                    for (int p = 0; p < 4; p++)
                        acc[q][p] = fma2(dv[2 * p + kw], wp, acc[q][p]);
                }
            }
        }
    }

#pragma unroll
    for (int q = 0; q < 4; q++) {
        const int co0 = cog + 2 * q;
        const float b0 = __ldg(bias + co0);
        const float b1 = __ldg(bias + co0 + 1);
#pragma unroll
        for (int p = 0; p < 4; p++) {
            const int w = w0 + p;
            if (w < HOUT) {
                const float2 v = unpack2(acc[q][p]);
                outp[((size_t)co0       * HOUT + h) * HOUT + w] = fmaxf(v.x + b0, 0.f);
                outp[((size_t)(co0 + 1) * HOUT + h) * HOUT + w] = fmaxf(v.y + b1, 0.f);
            }
        }
    }
}

// Layer 1: 3x84x84 -> 64x42x42, tasks/img = 42*11 = 462 (4 blocks of 128)
__global__ void __launch_bounds__(128, 4)
conv1_k(const float* __restrict__ xs, const float* __restrict__ xt,
        const float* __restrict__ W, const float* __restrict__ b)
{
    const int n   = blockIdx.z;
    const int cog = blockIdx.y * 8;
    const int task = blockIdx.x * 128 + threadIdx.x;
    const float* base = (n < NSUP) ? xs + (size_t)n * 3 * 84 * 84
                                   : xt + (size_t)(n - NSUP) * 3 * 84 * 84;
    conv_body<3, 84, 42, 0, 128>(base, W, b, g_a1 + (size_t)n * 64 * 42 * 42, cog, task);
}

// Layer 2: 64x42x42 -> 64x21x21, tasks/img = 21*6 = 126 (one block)
__global__ void __launch_bounds__(128, 4)
conv2_k(const float* __restrict__ W, const float* __restrict__ b)
{
    const int n = blockIdx.y, cog = blockIdx.x * 8;
    conv_body<64, 42, 21, 0, 128>(g_a1 + (size_t)n * 64 * 42 * 42, W, b,
                                  g_a2 + (size_t)n * 64 * 21 * 21, cog, threadIdx.x);
}

// Layer 3: 64x21x21 -> 64x11x11, tasks/img = 11*3 = 33 ; 4 images per block
__global__ void __launch_bounds__(132, 4)
conv3_k(const float* __restrict__ W, const float* __restrict__ b)
{
    const int il = threadIdx.x / 33;          // 0..3
    const int task = threadIdx.x % 33;
    const int n = blockIdx.y * 4 + il;
    const int cog = blockIdx.x * 8;
    conv_body<64, 21, 11, 1, 132>(g_a2 + (size_t)n * 64 * 21 * 21, W, b,
                                  g_a3 + (size_t)n * 64 * 11 * 11, cog, task);
}

// Layer 4: 64x11x11 -> 64x6x6, tasks/img = 6*2 = 12 ; 10 images per block
__global__ void __launch_bounds__(120, 4)
conv4_k(const float* __restrict__ W, const float* __restrict__ b)
{
    const int il = threadIdx.x / 12;          // 0..9
    const int task = threadIdx.x % 12;
    const int n = blockIdx.y * 10 + il;
    const int cog = blockIdx.x * 8;
    conv_body<64, 11, 6, 1, 120>(g_a3 + (size_t)n * 64 * 11 * 11, W, b,
                                 g_emb + (size_t)n * DFEAT, cog, task);
}

// Prototypes: proto[b][c][d] = sum_{s: y[b,s]%5==c} emb[b,s,d] / CAP,  CAP=5.
// Also computes ||proto|| per (b,c).  grid = 40 blocks, 256 threads.
__global__ void proto_k(const int* __restrict__ y)
{
    const int b = blockIdx.x / CCLS;
    const int c = blockIdx.x % CCLS;
    const int tid = threadIdx.x;
    __shared__ float sel[SSUP];
    if (tid < SSUP)
        sel[tid] = ((y[b * SSUP + tid] % CCLS) == c) ? 0.2f : 0.f;  // 1/CAP folded in
    __syncthreads();

    float sq = 0.f;
    for (int d = tid; d < DFEAT; d += 256) {
        float s = 0.f;
#pragma unroll 5
        for (int k = 0; k < SSUP; k++)
            s += sel[k] * g_emb[(size_t)(b * SSUP + k) * DFEAT + d];
        g_protos[(size_t)(b * CCLS + c) * DFEAT + d] = s;
        sq += s * s;
    }
    __shared__ float red[256];
    red[tid] = sq;
    __syncthreads();
    for (int off = 128; off > 0; off >>= 1) {
        if (tid < off) red[tid] += red[tid + off];
        __syncthreads();
    }
    if (tid == 0) g_pnorm[blockIdx.x] = sqrtf(red[0]);
}

// Cosine logits: out[b,t,c] = (t . p_c) / (max(|t|,eps) * max(|p_c|,eps))
// grid = 600 blocks (one per (b,t)), 128 threads.
__global__ void preds_k(float* __restrict__ out)
{
    const int bt = blockIdx.x;
    const int b  = bt / TTGT;
    const int tid = threadIdx.x;
    const float* te = g_emb + (size_t)(NSUP + bt) * DFEAT;
    const float* pr = g_protos + (size_t)b * CCLS * DFEAT;

    float dot[CCLS] = {0.f, 0.f, 0.f, 0.f, 0.f};
    float nn = 0.f;
    for (int d = tid; d < DFEAT; d += 128) {
        const float tv = te[d];
        nn += tv * tv;
#pragma unroll
        for (int c = 0; c < CCLS; c++)
            dot[c] += tv * pr[(size_t)c * DFEAT + d];
    }

    __shared__ float red[6][128];
    red[0][tid] = nn;
#pragma unroll
    for (int c = 0; c < CCLS; c++) red[c + 1][tid] = dot[c];
    __syncthreads();
    for (int off = 64; off > 0; off >>= 1) {
        if (tid < off) {
#pragma unroll
            for (int j = 0; j < 6; j++) red[j][tid] += red[j][tid + off];
        }
        __syncthreads();
    }
    if (tid < CCLS) {
        const float tn = fmaxf(sqrtf(red[0][0]), EPSN);
        const float pn = fmaxf(g_pnorm[b * CCLS + tid], EPSN);
        out[bt * CCLS + tid] = red[1 + tid][0] / (tn * pn);
    }
}

extern "C" void kernel_launch(void* const* d_in, const int* in_sizes, int n_in,
                              void* d_out, int out_size)
{
    (void)in_sizes; (void)n_in; (void)out_size;
    const float* xs = (const float*)d_in[0];   // [8,25,3,84,84]
    const float* xt = (const float*)d_in[1];   // [8,75,3,84,84]
    const int*   y  = (const int*)d_in[2];     // [8,25]
    const float* W1 = (const float*)d_in[3];
    const float* b1 = (const float*)d_in[4];
    const float* W2 = (const float*)d_in[5];
    const float* b2 = (const float*)d_in[6];
    const float* W3 = (const float*)d_in[7];
    const float* b3 = (const float*)d_in[8];
    const float* W4 = (const float*)d_in[9];
    const float* b4 = (const float*)d_in[10];
    float* out = (float*)d_out;

    conv1_k<<<dim3(4, 8, NIMG), 128>>>(xs, xt, W1, b1);
    conv2_k<<<dim3(8, NIMG), 128>>>(W2, b2);
    conv3_k<<<dim3(8, NIMG / 4), 132>>>(W3, b3);
    conv4_k<<<dim3(8, NIMG / 10), 120>>>(W4, b4);

    proto_k<<<BN * CCLS, 256>>>(y);
    preds_k<<<BN * TTGT, 128>>>(out);
}

// round 7
// speedup vs baseline: 1.4827x; 1.1466x over previous
#include <cuda_runtime.h>
#include <math.h>

#define BN    8
#define SSUP  25
#define TTGT  75
#define CCLS  5
#define NIMG  800     // 200 support + 600 target
#define NSUP  200
#define DFEAT 2304
#define EPSN  1e-8f

typedef unsigned long long u64;

// Padded intermediate layouts (zero borders, vector-load friendly):
// A1: [64][44][44] valid [0..41][0..41]          (conv2 reads idx 2h+kh <= 42)
// A2: [64][24][24] valid at [h+1][w+1], h,w<=20  (conv3: shift folds pad=1)
// A3: [64][14][16] valid at [h+1][w+1], h,w<=10  (conv4)
#define A1_RS 44
#define A1_PS (44*44)
#define A1_IMG (64*A1_PS)
#define A2_RS 24
#define A2_PS (24*24)
#define A2_IMG (64*A2_PS)
#define A3_RS 16
#define A3_PS (14*16)
#define A3_IMG (64*A3_PS)

__device__ float g_a1[NIMG * A1_IMG + 64];
__device__ float g_a2[NIMG * A2_IMG + 64];
__device__ float g_a3[NIMG * A3_IMG + 64];
__device__ float g_emb[NIMG * DFEAT];
__device__ float g_protos[BN * CCLS * DFEAT];
__device__ float g_pnorm[BN * CCLS];

// ---- packed f32x2 helpers (sm_103a FFMA2 path) ----
__device__ __forceinline__ u64 dup2(float v) {
    u64 r; unsigned u = __float_as_uint(v);
    asm("mov.b64 %0, {%1, %2};" : "=l"(r) : "r"(u), "r"(u));
    return r;
}
__device__ __forceinline__ u64 fma2(u64 a, u64 b, u64 c) {
    u64 d;
    asm("fma.rn.f32x2 %0, %1, %2, %3;" : "=l"(d) : "l"(a), "l"(b), "l"(c));
    return d;
}
__device__ __forceinline__ float2 unpack2(u64 v) {
    unsigned lo, hi;
    asm("mov.b64 {%0, %1}, %2;" : "=r"(lo), "=r"(hi) : "l"(v));
    return make_float2(__uint_as_float(lo), __uint_as_float(hi));
}

// Zero the padding borders of A1/A2/A3 (never touched by conv writers).
__global__ void zero_borders_k()
{
    const long long id = (long long)blockIdx.x * 256 + threadIdx.x;
    const int which = blockIdx.y;
    if (which == 0) {                         // A1: 172 border cells / chan
        if (id >= (long long)NIMG * 64 * 172) return;
        const int j = (int)(id % 172);
        const long long nc = id / 172;        // img*64 + ch
        int r, c;
        if (j < 88) { r = 42 + j / 44; c = j % 44; }
        else { int j2 = j - 88; r = j2 >> 1; c = 42 + (j2 & 1); }
        g_a1[nc * A1_PS + r * A1_RS + c] = 0.f;
    } else if (which == 1) {                  // A2: 135 border cells / chan
        if (id >= (long long)NIMG * 64 * 135) return;
        const int j = (int)(id % 135);
        const long long nc = id / 135;
        int r, c;
        if (j < 72) { int rs = j / 24; r = (rs == 0) ? 0 : 21 + rs; c = j % 24; }
        else { int j2 = j - 72; r = 1 + j2 / 3; int m = j2 % 3; c = (m == 0) ? 0 : 21 + m; }
        g_a2[nc * A2_PS + r * A2_RS + c] = 0.f;
    } else {                                  // A3: 103 border cells / chan
        if (id >= (long long)NIMG * 64 * 103) return;
        const int j = (int)(id % 103);
        const long long nc = id / 103;
        int r, c;
        if (j < 48) { int rs = j / 16; r = (rs == 0) ? 0 : 11 + rs; c = j % 16; }
        else { int j2 = j - 48; r = 1 + j2 / 5; int m = j2 % 5; c = (m == 0) ? 0 : 11 + m; }
        g_a3[nc * A3_PS + r * A3_RS + c] = 0.f;
    }
}

// Vectorized direct conv for padded inputs: stride 2, 3x3, no bounds checks.
// Weights for an 8-cout group staged in smem as [cin][k][oc]; input rows read
// as 3 aligned float4 (over-read lanes feed only discarded accumulators).
// Each thread: 4 oc-pairs (FFMA2) x 4 output pixels.
template <int CIN, int RS, int PS, int HOUT, int ORS, int OPS, int OSH, int TPB>
__device__ __forceinline__ void conv_body_v(
    const float* __restrict__ base,    // image-local padded input
    const float* __restrict__ W,       // [64,CIN,3,3]
    const float* __restrict__ bias,
    float* __restrict__ outp,          // image-local output
    int cog, int task)
{
    constexpr int WT = (HOUT + 3) / 4;
    const int tid = threadIdx.x;

    __shared__ __align__(16) float sw[8 * CIN * 9];   // [cin][k][oc]
    for (int i = tid; i < 8 * CIN * 9; i += TPB) {
        const int oc  = i & 7;
        const int k   = (i >> 3) % 9;
        const int cin = i / 72;
        sw[i] = __ldg(W + ((size_t)(cog + oc) * CIN + cin) * 9 + k);
    }
    __syncthreads();

    if (task >= HOUT * WT) return;
    const int h  = task / WT;
    const int w0 = (task % WT) * 4;
    const int r0 = 2 * h;
    const int c0 = 2 * w0;

    u64 acc[4][4];
#pragma unroll
    for (int q = 0; q < 4; q++)
#pragma unroll
        for (int p = 0; p < 4; p++) acc[q][p] = 0ull;

    for (int cin = 0; cin < CIN; cin++) {
        const float* ip = base + (size_t)cin * PS + (size_t)r0 * RS + c0;
#pragma unroll
        for (int kh = 0; kh < 3; kh++) {
            const float4 f0 = *(const float4*)(ip + kh * RS);
            const float4 f1 = *(const float4*)(ip + kh * RS + 4);
            const float4 f2 = *(const float4*)(ip + kh * RS + 8);
            u64 dv[9];
            dv[0] = dup2(f0.x); dv[1] = dup2(f0.y); dv[2] = dup2(f0.z); dv[3] = dup2(f0.w);
            dv[4] = dup2(f1.x); dv[5] = dup2(f1.y); dv[6] = dup2(f1.z); dv[7] = dup2(f1.w);
            dv[8] = dup2(f2.x);
#pragma unroll
            for (int kw = 0; kw < 3; kw++) {
                const u64* wrow = (const u64*)&sw[cin * 72 + (kh * 3 + kw) * 8];
#pragma unroll
                for (int q = 0; q < 4; q++) {
                    const u64 wp = wrow[q];
#pragma unroll
                    for (int p = 0; p < 4; p++)
                        acc[q][p] = fma2(dv[2 * p + kw], wp, acc[q][p]);
                }
            }
        }
    }

#pragma unroll
    for (int q = 0; q < 4; q++) {
        const int co0 = cog + 2 * q;
        const float b0 = __ldg(bias + co0);
        const float b1 = __ldg(bias + co0 + 1);
#pragma unroll
        for (int p = 0; p < 4; p++) {
            const int w = w0 + p;
            if (w < HOUT) {
                const float2 v = unpack2(acc[q][p]);
                outp[((size_t)co0       * OPS) + (h + OSH) * ORS + (w + OSH)] = fmaxf(v.x + b0, 0.f);
                outp[((size_t)(co0 + 1) * OPS) + (h + OSH) * ORS + (w + OSH)] = fmaxf(v.y + b1, 0.f);
            }
        }
    }
}

// Layer 1 (harness input, unpadded -> masked scalar loads), writes padded A1.
__global__ void __launch_bounds__(128)
conv1_k(const float* __restrict__ xs, const float* __restrict__ xt,
        const float* __restrict__ W, const float* __restrict__ b)
{
    const int n   = blockIdx.z;
    const int cog = blockIdx.y * 8;
    const int tid = threadIdx.x;
    const int task = blockIdx.x * 128 + tid;

    __shared__ __align__(16) float sw[8 * 3 * 9];
    for (int i = tid; i < 8 * 3 * 9; i += 128) {
        const int oc = i & 7, k = (i >> 3) % 9, cin = i / 72;
        sw[i] = __ldg(W + ((size_t)(cog + oc) * 3 + cin) * 9 + k);
    }
    __syncthreads();

    if (task >= 42 * 11) return;
    const int h  = task / 11;
    const int w0 = (task % 11) * 4;
    const int r0 = 2 * h, c0 = 2 * w0;

    const float* base = (n < NSUP) ? xs + (size_t)n * 3 * 84 * 84
                                   : xt + (size_t)(n - NSUP) * 3 * 84 * 84;
    float* outp = g_a1 + (size_t)n * A1_IMG;

    u64 acc[4][4];
#pragma unroll
    for (int q = 0; q < 4; q++)
#pragma unroll
        for (int p = 0; p < 4; p++) acc[q][p] = 0ull;

#pragma unroll
    for (int cin = 0; cin < 3; cin++) {
        const float* ip = base + (size_t)cin * 84 * 84;
#pragma unroll
        for (int kh = 0; kh < 3; kh++) {
            const int r = r0 + kh;
            const bool rok = (r < 84);
            u64 dv[9];
#pragma unroll
            for (int kc = 0; kc < 9; kc++) {
                const int c = c0 + kc;
                const float v = (rok && c < 84) ? __ldg(ip + r * 84 + c) : 0.f;
                dv[kc] = dup2(v);
            }
#pragma unroll
            for (int kw = 0; kw < 3; kw++) {
                const u64* wrow = (const u64*)&sw[cin * 72 + (kh * 3 + kw) * 8];
#pragma unroll
                for (int q = 0; q < 4; q++) {
                    const u64 wp = wrow[q];
#pragma unroll
                    for (int p = 0; p < 4; p++)
                        acc[q][p] = fma2(dv[2 * p + kw], wp, acc[q][p]);
                }
            }
        }
    }

#pragma unroll
    for (int q = 0; q < 4; q++) {
        const int co0 = cog + 2 * q;
        const float b0 = __ldg(b + co0);
        const float b1 = __ldg(b + co0 + 1);
#pragma unroll
        for (int p = 0; p < 4; p++) {
            const int w = w0 + p;
            if (w < 42) {
                const float2 v = unpack2(acc[q][p]);
                outp[(size_t)co0       * A1_PS + h * A1_RS + w] = fmaxf(v.x + b0, 0.f);
                outp[(size_t)(co0 + 1) * A1_PS + h * A1_RS + w] = fmaxf(v.y + b1, 0.f);
            }
        }
    }
}

// Layer 2: A1 -> A2, 126 tasks/img, 2 img/block (256 threads)
__global__ void __launch_bounds__(256)
conv2_k(const float* __restrict__ W, const float* __restrict__ b)
{
    const int il = threadIdx.x >> 7;
    const int task = threadIdx.x & 127;
    const int n = blockIdx.y * 2 + il;
    const int cog = blockIdx.x * 8;
    conv_body_v<64, A1_RS, A1_PS, 21, A2_RS, A2_PS, 1, 256>(
        g_a1 + (size_t)n * A1_IMG, W, b, g_a2 + (size_t)n * A2_IMG, cog, task);
}

// Layer 3: A2 -> A3, 33 tasks/img, 8 img/block (264 threads)
__global__ void __launch_bounds__(264)
conv3_k(const float* __restrict__ W, const float* __restrict__ b)
{
    const int il = threadIdx.x / 33;
    const int task = threadIdx.x % 33;
    const int n = blockIdx.y * 8 + il;
    const int cog = blockIdx.x * 8;
    conv_body_v<64, A2_RS, A2_PS, 11, A3_RS, A3_PS, 1, 264>(
        g_a2 + (size_t)n * A2_IMG, W, b, g_a3 + (size_t)n * A3_IMG, cog, task);
}

// Layer 4: A3 -> emb (dense), 12 tasks/img, 20 img/block (240 threads)
__global__ void __launch_bounds__(240)
conv4_k(const float* __restrict__ W, const float* __restrict__ b)
{
    const int il = threadIdx.x / 12;
    const int task = threadIdx.x % 12;
    const int n = blockIdx.y * 20 + il;
    const int cog = blockIdx.x * 8;
    conv_body_v<64, A3_RS, A3_PS, 6, 6, 36, 0, 240>(
        g_a3 + (size_t)n * A3_IMG, W, b, g_emb + (size_t)n * DFEAT, cog, task);
}

// Prototypes: proto[b][c][d] = sum_{s: y%5==c} emb / CAP ; plus ||proto||.
__global__ void proto_k(const int* __restrict__ y)
{
    const int b = blockIdx.x / CCLS;
    const int c = blockIdx.x % CCLS;
    const int tid = threadIdx.x;
    __shared__ float sel[SSUP];
    if (tid < SSUP)
        sel[tid] = ((y[b * SSUP + tid] % CCLS) == c) ? 0.2f : 0.f;
    __syncthreads();

    float sq = 0.f;
    for (int d = tid; d < DFEAT; d += 256) {
        float s = 0.f;
#pragma unroll 5
        for (int k = 0; k < SSUP; k++)
            s += sel[k] * g_emb[(size_t)(b * SSUP + k) * DFEAT + d];
        g_protos[(size_t)(b * CCLS + c) * DFEAT + d] = s;
        sq += s * s;
    }
    __shared__ float red[256];
    red[tid] = sq;
    __syncthreads();
    for (int off = 128; off > 0; off >>= 1) {
        if (tid < off) red[tid] += red[tid + off];
        __syncthreads();
    }
    if (tid == 0) g_pnorm[blockIdx.x] = sqrtf(red[0]);
}

// Cosine logits
__global__ void preds_k(float* __restrict__ out)
{
    const int bt = blockIdx.x;
    const int b  = bt / TTGT;
    const int tid = threadIdx.x;
    const float* te = g_emb + (size_t)(NSUP + bt) * DFEAT;
    const float* pr = g_protos + (size_t)b * CCLS * DFEAT;

    float dot[CCLS] = {0.f, 0.f, 0.f, 0.f, 0.f};
    float nn = 0.f;
    for (int d = tid; d < DFEAT; d += 128) {
        const float tv = te[d];
        nn += tv * tv;
#pragma unroll
        for (int c = 0; c < CCLS; c++)
            dot[c] += tv * pr[(size_t)c * DFEAT + d];
    }

    __shared__ float red[6][128];
    red[0][tid] = nn;
#pragma unroll
    for (int c = 0; c < CCLS; c++) red[c + 1][tid] = dot[c];
    __syncthreads();
    for (int off = 64; off > 0; off >>= 1) {
        if (tid < off) {
#pragma unroll
            for (int j = 0; j < 6; j++) red[j][tid] += red[j][tid + off];
        }
        __syncthreads();
    }
    if (tid < CCLS) {
        const float tn = fmaxf(sqrtf(red[0][0]), EPSN);
        const float pn = fmaxf(g_pnorm[b * CCLS + tid], EPSN);
        out[bt * CCLS + tid] = red[1 + tid][0] / (tn * pn);
    }
}

extern "C" void kernel_launch(void* const* d_in, const int* in_sizes, int n_in,
                              void* d_out, int out_size)
{
    (void)in_sizes; (void)n_in; (void)out_size;
    const float* xs = (const float*)d_in[0];
    const float* xt = (const float*)d_in[1];
    const int*   y  = (const int*)d_in[2];
    const float* W1 = (const float*)d_in[3];
    const float* b1 = (const float*)d_in[4];
    const float* W2 = (const float*)d_in[5];
    const float* b2 = (const float*)d_in[6];
    const float* W3 = (const float*)d_in[7];
    const float* b3 = (const float*)d_in[8];
    const float* W4 = (const float*)d_in[9];
    const float* b4 = (const float*)d_in[10];
    float* out = (float*)d_out;

    // Zero pad borders of A1/A2/A3 (max cells: 800*64*172 -> 34400 blocks)
    zero_borders_k<<<dim3(34400, 3), 256>>>();

    conv1_k<<<dim3(4, 8, NIMG), 128>>>(xs, xt, W1, b1);
    conv2_k<<<dim3(8, NIMG / 2), 256>>>(W2, b2);
    conv3_k<<<dim3(8, NIMG / 8), 264>>>(W3, b3);
    conv4_k<<<dim3(8, NIMG / 20), 240>>>(W4, b4);

    proto_k<<<BN * CCLS, 256>>>(y);
    preds_k<<<BN * TTGT, 128>>>(out);
}